// round 12
// baseline (speedup 1.0000x reference)
#include <cuda_runtime.h>
#include <math_constants.h>
#include <cstdint>

#define BB   8
#define NN   2048
#define DIN  256
#define DOUT 128
#define TOPK 16

__device__ float g_w2p[4 * DIN];
__device__ float g_sj[BB * NN];
__device__ float g_v[BB * DOUT];
__device__ int   g_vflag[BB];

// order-preserving float->uint key (bigger float => bigger key; finite keys > 0)
__device__ __forceinline__ unsigned fkey(float f) {
    unsigned b = __float_as_uint(f);
    return b ^ (((int)b >> 31) | 0x80000000u);
}
__device__ __forceinline__ float fkey_inv(unsigned k) {
    unsigned b = (k & 0x80000000u) ? (k ^ 0x80000000u) : ~k;
    return __uint_as_float(b);
}

// ---------------------------------------------------------------------------
// K0: w2 partials (4 blocks) + per-batch flag reset for this replay.
// ---------------------------------------------------------------------------
__global__ void __launch_bounds__(256) k0_w2(const float* __restrict__ W,
                                             const float* __restrict__ a) {
    cudaTriggerProgrammaticLaunchCompletion();
    int i = threadIdx.x;
    if (blockIdx.x == 0 && i < BB) g_vflag[i] = 0;
    int o0 = blockIdx.x * 32;
    float s0 = 0.f, s1 = 0.f, s2 = 0.f, s3 = 0.f;
#pragma unroll
    for (int q = 0; q < 32; q += 4) {
        s0 += W[(o0 + q    ) * DIN + i] * __ldg(a + DOUT + o0 + q);
        s1 += W[(o0 + q + 1) * DIN + i] * __ldg(a + DOUT + o0 + q + 1);
        s2 += W[(o0 + q + 2) * DIN + i] * __ldg(a + DOUT + o0 + q + 2);
        s3 += W[(o0 + q + 3) * DIN + i] * __ldg(a + DOUT + o0 + q + 3);
    }
    g_w2p[blockIdx.x * DIN + i] = (s0 + s1) + (s2 + s3);
}

// ---------------------------------------------------------------------------
// K1: sj = x . w2.  512 blocks x 256 thr; warp = 4 rows, loads front-issued
// before the PDL grid sync; interleaved shuffle reductions.  (R5 verbatim.)
// ---------------------------------------------------------------------------
__global__ void __launch_bounds__(256) k1_sj(const float* __restrict__ x) {
    cudaTriggerProgrammaticLaunchCompletion();
    __shared__ float w2s[DIN];
    int tid = threadIdx.x;
    int lane = tid & 31, warp = tid >> 5;
    int r0 = blockIdx.x * 32 + warp * 4;

    const float4* x4 = reinterpret_cast<const float4*>(x);
    size_t base = (size_t)r0 * (DIN / 4);

    float4 a0 = x4[base        + lane];
    float4 b0 = x4[base        + lane + 32];
    float4 a1 = x4[base + 64   + lane];
    float4 b1 = x4[base + 64   + lane + 32];
    float4 a2 = x4[base + 128  + lane];
    float4 b2 = x4[base + 128  + lane + 32];
    float4 a3 = x4[base + 192  + lane];
    float4 b3 = x4[base + 192  + lane + 32];

    cudaGridDependencySynchronize();

    w2s[tid] = g_w2p[tid] + g_w2p[DIN + tid] + g_w2p[2 * DIN + tid] + g_w2p[3 * DIN + tid];
    __syncthreads();

    const float4* w4 = reinterpret_cast<const float4*>(w2s);
    float4 wa = w4[lane];
    float4 wb = w4[lane + 32];

    float s0 = a0.x*wa.x + a0.y*wa.y + a0.z*wa.z + a0.w*wa.w
             + b0.x*wb.x + b0.y*wb.y + b0.z*wb.z + b0.w*wb.w;
    float s1 = a1.x*wa.x + a1.y*wa.y + a1.z*wa.z + a1.w*wa.w
             + b1.x*wb.x + b1.y*wb.y + b1.z*wb.z + b1.w*wb.w;
    float s2 = a2.x*wa.x + a2.y*wa.y + a2.z*wa.z + a2.w*wa.w
             + b2.x*wb.x + b2.y*wb.y + b2.z*wb.z + b2.w*wb.w;
    float s3 = a3.x*wa.x + a3.y*wa.y + a3.z*wa.z + a3.w*wa.w
             + b3.x*wb.x + b3.y*wb.y + b3.z*wb.z + b3.w*wb.w;

#pragma unroll
    for (int o = 16; o; o >>= 1) {
        s0 += __shfl_xor_sync(0xffffffffu, s0, o);
        s1 += __shfl_xor_sync(0xffffffffu, s1, o);
        s2 += __shfl_xor_sync(0xffffffffu, s2, o);
        s3 += __shfl_xor_sync(0xffffffffu, s3, o);
    }
    if (lane < 4) {
        float s = (lane == 0) ? s0 : (lane == 1) ? s1 : (lane == 2) ? s2 : s3;
        g_sj[r0 + lane] = s;
    }
}

// ---------------------------------------------------------------------------
// K2: blocks 0..7 select; blocks 8..519 write output when their batch's v
// is published.  New select: thread-max pruning -> one-warp top-16-threads
// (redux, no syncs) -> 128-candidate rank-count.
// ---------------------------------------------------------------------------
__global__ void __launch_bounds__(256) k2_select_out(const float* __restrict__ x,
                                                     const float* __restrict__ W,
                                                     float* __restrict__ out) {
    int tid = threadIdx.x;
    int lane = tid & 31;

    cudaGridDependencySynchronize();   // k1's g_sj visible; flags reset by k0

    if (blockIdx.x < BB) {
        __shared__ unsigned tm_k[256];
        __shared__ int      sel_t[TOPK];
        __shared__ unsigned cand_k[128];
        __shared__ int      cand_j[128];
        __shared__ unsigned sel_k[TOPK];
        __shared__ int      sel_j[TOPK];
        __shared__ float    attn[TOPK];
        __shared__ float    xbar[DIN];

        int b = blockIdx.x;

        // ---- 1: per-thread 8 contiguous scores (2x float4), local max ----
        const float4* sj4 = reinterpret_cast<const float4*>(g_sj + b * NN) + tid * 2;
        float4 v0 = sj4[0], v1 = sj4[1];
        unsigned key[8];
        key[0] = fkey(v0.x); key[1] = fkey(v0.y); key[2] = fkey(v0.z); key[3] = fkey(v0.w);
        key[4] = fkey(v1.x); key[5] = fkey(v1.y); key[6] = fkey(v1.z); key[7] = fkey(v1.w);
        unsigned m01 = max(key[0], key[1]), m23 = max(key[2], key[3]);
        unsigned m45 = max(key[4], key[5]), m67 = max(key[6], key[7]);
        tm_k[tid] = max(max(m01, m23), max(m45, m67));
        __syncthreads();

        // ---- 2: one warp picks top-16 THREADS by thread-max (no syncs) ----
        if (tid < 32) {
            unsigned km[8];
#pragma unroll
            for (int t = 0; t < 8; ++t) km[t] = tm_k[t * 32 + tid];
#pragma unroll 1
            for (int k = 0; k < TOPK; ++k) {
                unsigned a01 = max(km[0], km[1]), a23 = max(km[2], km[3]);
                unsigned a45 = max(km[4], km[5]), a67 = max(km[6], km[7]);
                unsigned loc = max(max(a01, a23), max(a45, a67));
                unsigned m = __reduce_max_sync(0xffffffffu, loc);
                unsigned jc = 0xFFFFFFFFu;
#pragma unroll
                for (int t = 0; t < 8; ++t)
                    if (km[t] == m) jc = min(jc, (unsigned)(t * 32 + tid));
                unsigned jmin = __reduce_min_sync(0xffffffffu, jc);
                if ((jmin & 31u) == (unsigned)tid) km[jmin >> 5] = 0u;  // owner clears
                if (tid == 0) sel_t[k] = (int)jmin;
            }
        }
        __syncthreads();

        // ---- 3: selected threads dump their 8 (key, j) pairs ----
        int slot = -1;
#pragma unroll
        for (int s = 0; s < TOPK; ++s)
            if (sel_t[s] == tid) slot = s;
        if (slot >= 0) {
#pragma unroll
            for (int t = 0; t < 8; ++t) {
                cand_k[slot * 8 + t] = key[t];
                cand_j[slot * 8 + t] = tid * 8 + t;
            }
        }
        __syncthreads();

        // ---- 4: rank-count over 128 candidates (index tiebreak) ----
        if (tid < 128) {
            unsigned mk = cand_k[tid];
            int      mj = cand_j[tid];
            int rank = 0;
#pragma unroll 16
            for (int c = 0; c < 128; ++c) {
                unsigned ck = cand_k[c];
                rank += (ck > mk) || (ck == mk && cand_j[c] < mj);
            }
            if (rank < TOPK) { sel_k[rank] = mk; sel_j[rank] = mj; }
        }
        __syncthreads();

        // ---- 5: warp softmax over 16 ----
        if (tid < TOPK) {
            float val = fkey_inv(sel_k[tid]);
            float m = val;
#pragma unroll
            for (int o = 8; o; o >>= 1) m = fmaxf(m, __shfl_xor_sync(0xffffu, m, o));
            float e = expf(val - m);
            float s = e;
#pragma unroll
            for (int o = 8; o; o >>= 1) s += __shfl_xor_sync(0xffffu, s, o);
            attn[tid] = e / s;
        }
        __syncthreads();

        // ---- 6: xbar[i] = sum_k attn[k] * x[b, sel_j[k], i] ----
        {
            float s0 = 0.f, s1 = 0.f;
#pragma unroll
            for (int k = 0; k < TOPK; k += 2) {
                s0 += attn[k]     * x[((size_t)b * NN + sel_j[k])     * DIN + tid];
                s1 += attn[k + 1] * x[((size_t)b * NN + sel_j[k + 1]) * DIN + tid];
            }
            xbar[tid] = s0 + s1;
        }
        __syncthreads();

        // ---- 7: v[d] = W[d,:] . xbar  (4 accumulators, short chain) ----
        if (tid < DOUT) {
            const float4* wr  = reinterpret_cast<const float4*>(W + tid * DIN);
            const float4* xb4 = reinterpret_cast<const float4*>(xbar);
            float c0 = 0.f, c1 = 0.f, c2 = 0.f, c3 = 0.f;
#pragma unroll
            for (int q = 0; q < DIN / 4; q += 4) {
                float4 w0 = wr[q],     p0 = xb4[q];
                float4 w1 = wr[q + 1], p1 = xb4[q + 1];
                float4 w2 = wr[q + 2], p2 = xb4[q + 2];
                float4 w3 = wr[q + 3], p3 = xb4[q + 3];
                c0 += w0.x*p0.x + w0.y*p0.y + w0.z*p0.z + w0.w*p0.w;
                c1 += w1.x*p1.x + w1.y*p1.y + w1.z*p1.z + w1.w*p1.w;
                c2 += w2.x*p2.x + w2.y*p2.y + w2.z*p2.z + w2.w*p2.w;
                c3 += w3.x*p3.x + w3.y*p3.y + w3.z*p3.z + w3.w*p3.w;
            }
            g_v[b * DOUT + tid] = (c0 + c1) + (c2 + c3);
        }
        __threadfence();
        __syncthreads();
        if (tid == 0) atomicExch(&g_vflag[b], 1);

    } else {
        int bid   = blockIdx.x - BB;   // 0..511
        int b     = bid >> 6;          // 64 blocks per batch
        int chunk = bid & 63;          // 32 rows each

        if (tid == 0) {
            volatile int* f = &g_vflag[b];
            while (*f == 0) {}
            __threadfence();
        }
        __syncthreads();

        float4 v = reinterpret_cast<const float4*>(g_v + b * DOUT)[lane];
        float4* o4 = reinterpret_cast<float4*>(out);
        size_t base = (size_t)b * (NN * DOUT / 4) + (size_t)chunk * 1024;
#pragma unroll
        for (int q = 0; q < 4; ++q)
            o4[base + q * 256 + tid] = v;
    }
}

// ---------------------------------------------------------------------------
extern "C" void kernel_launch(void* const* d_in, const int* in_sizes, int n_in,
                              void* d_out, int out_size) {
    const float* x = (const float*)d_in[0];   // [8, 2048, 256]
    const float* W = (const float*)d_in[1];   // [128, 256]
    const float* a = (const float*)d_in[2];   // [256]
    float* out = (float*)d_out;               // [8, 2048, 128]

    cudaLaunchAttribute attr[1];
    attr[0].id = cudaLaunchAttributeProgrammaticStreamSerialization;
    attr[0].val.programmaticStreamSerializationAllowed = 1;

    cudaLaunchConfig_t cfg = {};
    cfg.blockDim = {256, 1, 1};
    cfg.attrs = attr;
    cfg.numAttrs = 1;

    cfg.gridDim = {4, 1, 1};
    cudaLaunchKernelEx(&cfg, k0_w2, W, a);

    cfg.gridDim = {512, 1, 1};
    cudaLaunchKernelEx(&cfg, k1_sj, x);

    cfg.gridDim = {BB + 512, 1, 1};
    cudaLaunchKernelEx(&cfg, k2_select_out, x, W, out);
}

// round 14
// speedup vs baseline: 1.2259x; 1.2259x over previous
#include <cuda_runtime.h>
#include <math_constants.h>

#define BB   8
#define NN   2048
#define DIN  256
#define DOUT 128
#define TOPK 16

__device__ float g_w2p[4 * DIN];   // 4 partial w2 vectors
__device__ float g_sj[BB * NN];
__device__ float g_v[BB * DOUT];

// ---------------------------------------------------------------------------
// K0: partial w2.  Block p: g_w2p[p*256+i] = sum_{o in [32p,32p+32)} W[o,i]*a2[o]
// ---------------------------------------------------------------------------
__global__ void __launch_bounds__(256) k0_w2(const float* __restrict__ W,
                                             const float* __restrict__ a) {
    cudaTriggerProgrammaticLaunchCompletion();
    int i = threadIdx.x;
    int o0 = blockIdx.x * 32;
    float s = 0.f;
#pragma unroll
    for (int q = 0; q < 32; ++q)
        s += W[(o0 + q) * DIN + i] * __ldg(a + DOUT + o0 + q);
    g_w2p[blockIdx.x * DIN + i] = s;
}

// ---------------------------------------------------------------------------
// K1: sj[r] = x[r,:] . w2.  512 blocks x 256 thr; warp = 4 rows, 8 float4
// loads front-issued BEFORE the PDL grid sync (they don't depend on k0).
// ---------------------------------------------------------------------------
__global__ void __launch_bounds__(256) k1_sj(const float* __restrict__ x) {
    cudaTriggerProgrammaticLaunchCompletion();
    __shared__ float w2s[DIN];
    int tid = threadIdx.x;
    int lane = tid & 31, warp = tid >> 5;
    int r0 = blockIdx.x * 32 + warp * 4;

    const float4* x4 = reinterpret_cast<const float4*>(x);
    size_t base = (size_t)r0 * (DIN / 4);

    // Independent of k0 — issue while k0 may still be running.
    float4 a0 = x4[base        + lane];
    float4 b0 = x4[base        + lane + 32];
    float4 a1 = x4[base + 64   + lane];
    float4 b1 = x4[base + 64   + lane + 32];
    float4 a2 = x4[base + 128  + lane];
    float4 b2 = x4[base + 128  + lane + 32];
    float4 a3 = x4[base + 192  + lane];
    float4 b3 = x4[base + 192  + lane + 32];

    cudaGridDependencySynchronize();   // k0's g_w2p now visible

    w2s[tid] = g_w2p[tid] + g_w2p[DIN + tid] + g_w2p[2 * DIN + tid] + g_w2p[3 * DIN + tid];
    __syncthreads();

    const float4* w4 = reinterpret_cast<const float4*>(w2s);
    float4 wa = w4[lane];
    float4 wb = w4[lane + 32];

    float s0 = a0.x*wa.x + a0.y*wa.y + a0.z*wa.z + a0.w*wa.w
             + b0.x*wb.x + b0.y*wb.y + b0.z*wb.z + b0.w*wb.w;
    float s1 = a1.x*wa.x + a1.y*wa.y + a1.z*wa.z + a1.w*wa.w
             + b1.x*wb.x + b1.y*wb.y + b1.z*wb.z + b1.w*wb.w;
    float s2 = a2.x*wa.x + a2.y*wa.y + a2.z*wa.z + a2.w*wa.w
             + b2.x*wb.x + b2.y*wb.y + b2.z*wb.z + b2.w*wb.w;
    float s3 = a3.x*wa.x + a3.y*wa.y + a3.z*wa.z + a3.w*wa.w
             + b3.x*wb.x + b3.y*wb.y + b3.z*wb.z + b3.w*wb.w;

#pragma unroll
    for (int o = 16; o; o >>= 1) {
        s0 += __shfl_xor_sync(0xffffffffu, s0, o);
        s1 += __shfl_xor_sync(0xffffffffu, s1, o);
        s2 += __shfl_xor_sync(0xffffffffu, s2, o);
        s3 += __shfl_xor_sync(0xffffffffu, s3, o);
    }
    if (lane < 4) {
        float s = (lane == 0) ? s0 : (lane == 1) ? s1 : (lane == 2) ? s2 : s3;
        g_sj[r0 + lane] = s;
    }
}

// ---------------------------------------------------------------------------
// K2: per-batch select (8 blocks x 256 thr). Warp-local top-16 in registers,
// parallel rank-count merge (the top-16 SET suffices), warp softmax, gather
// xbar, v = W @ xbar.
// ---------------------------------------------------------------------------
__global__ void __launch_bounds__(256) k2_select(const float* __restrict__ x,
                                                 const float* __restrict__ W) {
    cudaTriggerProgrammaticLaunchCompletion();
    __shared__ float cand_v[128];
    __shared__ int   cand_j[128];
    __shared__ float sel_v[TOPK];
    __shared__ int   sel_j[TOPK];
    __shared__ float attn[TOPK];
    __shared__ float xbar[DIN];

    int b = blockIdx.x, tid = threadIdx.x;
    int lane = tid & 31, w = tid >> 5;

    cudaGridDependencySynchronize();   // k1's g_sj now visible

    float v[8];
    int base = b * NN + w * 256;
#pragma unroll
    for (int t = 0; t < 8; ++t) v[t] = g_sj[base + t * 32 + lane];

#pragma unroll 1
    for (int k = 0; k < TOPK; ++k) {
        float bv = v[0]; int bt = 0;
#pragma unroll
        for (int t = 1; t < 8; ++t)
            if (v[t] > bv) { bv = v[t]; bt = t; }
        int bj = bt * 32 + lane;
#pragma unroll
        for (int o = 16; o; o >>= 1) {
            float ov = __shfl_xor_sync(0xffffffffu, bv, o);
            int   oj = __shfl_xor_sync(0xffffffffu, bj, o);
            if (ov > bv) { bv = ov; bj = oj; }
        }
        if (lane == (bj & 31)) v[bj >> 5] = -CUDART_INF_F;
        if (lane == 0) { cand_v[w * TOPK + k] = bv; cand_j[w * TOPK + k] = w * 256 + bj; }
    }
    __syncthreads();

    if (tid < 128) {
        float mv = cand_v[tid];
        int   mj = cand_j[tid];
        int rank = 0;
#pragma unroll 8
        for (int c = 0; c < 128; ++c) rank += (cand_v[c] > mv);
        if (rank < TOPK) { sel_v[rank] = mv; sel_j[rank] = mj; }
    }
    __syncthreads();

    if (tid < TOPK) {
        float val = sel_v[tid];
        float m = val;
#pragma unroll
        for (int o = 8; o; o >>= 1) m = fmaxf(m, __shfl_xor_sync(0xffffu, m, o));
        float e = expf(val - m);
        float s = e;
#pragma unroll
        for (int o = 8; o; o >>= 1) s += __shfl_xor_sync(0xffffu, s, o);
        attn[tid] = e / s;
    }
    __syncthreads();

    {
        float s = 0.f;
#pragma unroll
        for (int k = 0; k < TOPK; ++k)
            s += attn[k] * x[((size_t)b * NN + sel_j[k]) * DIN + tid];
        xbar[tid] = s;
    }
    __syncthreads();

    if (tid < DOUT) {
        const float4* wr  = reinterpret_cast<const float4*>(W + tid * DIN);
        const float4* xb4 = reinterpret_cast<const float4*>(xbar);
        float s = 0.f;
#pragma unroll
        for (int q = 0; q < DIN / 4; ++q) {
            float4 wv = wr[q], xv = xb4[q];
            s += wv.x * xv.x + wv.y * xv.y + wv.z * xv.z + wv.w * xv.w;
        }
        g_v[b * DOUT + tid] = s;
    }
}

// ---------------------------------------------------------------------------
// K3: out[b,n,:] = v[b,:] broadcast. 512 blocks x 256 thr, 4 float4 stores
// per thread. Launches during k2 (PDL); syncs before reading g_v.
// ---------------------------------------------------------------------------
__global__ void __launch_bounds__(256) k3_out(float* __restrict__ out) {
    int blk = blockIdx.x;            // 0..511
    int b     = blk >> 6;            // 64 blocks per batch
    int chunk = blk & 63;            // 32 rows per block
    int tid = threadIdx.x;

    cudaGridDependencySynchronize();  // k2's g_v now visible

    float4 v = reinterpret_cast<const float4*>(g_v + b * DOUT)[tid & 31];
    float4* o4 = reinterpret_cast<float4*>(out);
    size_t base = (size_t)b * (NN * DOUT / 4) + (size_t)chunk * 1024;
#pragma unroll
    for (int q = 0; q < 4; ++q)
        o4[base + q * 256 + tid] = v;
}

// ---------------------------------------------------------------------------
extern "C" void kernel_launch(void* const* d_in, const int* in_sizes, int n_in,
                              void* d_out, int out_size) {
    const float* x = (const float*)d_in[0];   // [8, 2048, 256]
    const float* W = (const float*)d_in[1];   // [128, 256]
    const float* a = (const float*)d_in[2];   // [256]
    float* out = (float*)d_out;               // [8, 2048, 128]

    cudaLaunchAttribute attr[1];
    attr[0].id = cudaLaunchAttributeProgrammaticStreamSerialization;
    attr[0].val.programmaticStreamSerializationAllowed = 1;

    cudaLaunchConfig_t cfg = {};
    cfg.blockDim = {256, 1, 1};
    cfg.attrs = attr;
    cfg.numAttrs = 1;

    cfg.gridDim = {4, 1, 1};
    cudaLaunchKernelEx(&cfg, k0_w2, W, a);

    cfg.gridDim = {512, 1, 1};
    cudaLaunchKernelEx(&cfg, k1_sj, x);

    cfg.gridDim = {BB, 1, 1};
    cudaLaunchKernelEx(&cfg, k2_select, x, W);

    cfg.gridDim = {512, 1, 1};
    cudaLaunchKernelEx(&cfg, k3_out, out);
}